// round 13
// baseline (speedup 1.0000x reference)
#include <cuda_runtime.h>
#include <cuda_fp16.h>
#include <stdint.h>

// Problem constants
#define BATCH   512
#define IN_FLAT 1024
#define NEURONS 4096
#define FOCUS   64

// GEMM tiling (fp16 m16n8k16)
#define BM 128
#define BN 128
#define BK 128
#define TPB 128                    // 4 warps (2m x 2n), warp tile 64x64
#define KTILES (IN_FLAT / BK)      // 8
#define STAGES 3
#define STAGE_BYTES 65536          // A 32KB + B 32KB (fp16)
#define OF_B 32768
#define OF_BIAS (STAGES * STAGE_BYTES)          // 196608
#define SMEM_DYN (OF_BIAS + BN * 4)             // 197120

// Fragment-packed operands (uint4 chunks; device globals, no allocation)
// A chunk (kt16, m16, lane) = {a0,a1,a2,a3} of m16n8k16   -> 64*32*32 uint4 = 1 MB
// B chunk (kt16, n16, lane) = {b0,b1 of n8 j0, b0,b1 j1}  -> 64*256*32 uint4 = 8 MB
__device__ uint4 g_xA[64 * 32 * 32];
__device__ uint4 g_WB[64 * 256 * 32];

// ---------------------------------------------------------------------------
__device__ __forceinline__ uint32_t smem_u32(const void* p) {
    uint32_t a;
    asm("{ .reg .u64 t; cvta.to.shared.u64 t, %1; cvt.u32.u64 %0, t; }" : "=r"(a) : "l"(p));
    return a;
}
__device__ __forceinline__ uint32_t pack_h2(float lo, float hi) {
    __half2 h = __floats2half2_rn(lo, hi);
    return *(uint32_t*)&h;
}
__device__ __forceinline__ void cp_async16(uint32_t sdst, const void* gsrc) {
    asm volatile("cp.async.cg.shared.global [%0], [%1], 16;"
                 :: "r"(sdst), "l"(__cvta_generic_to_global(gsrc)) : "memory");
}
__device__ __forceinline__ void mma_f16(float* c, const uint4& a,
                                        uint32_t b0, uint32_t b1) {
    asm volatile(
        "mma.sync.aligned.m16n8k16.row.col.f32.f16.f16.f32 "
        "{%0,%1,%2,%3}, {%4,%5,%6,%7}, {%8,%9}, {%0,%1,%2,%3};"
        : "+f"(c[0]), "+f"(c[1]), "+f"(c[2]), "+f"(c[3])
        : "r"(a.x), "r"(a.y), "r"(a.z), "r"(a.w), "r"(b0), "r"(b1));
}

// ---------------------------------------------------------------------------
// Merged prep kernel (256 threads/block, grid 768):
//   blocks [0,512):   densify 8 W rows each -> g_WB fp16 fragment half-chunks
//   blocks [512,768): convert x             -> g_xA fp16 fragment chunks
// 8-row densify blocks write disjoint 8B halves of each B uint4 (j0 vs j1).
#define DSTR 1044                          // padded row stride (floats)
#define D_SM_FLOATS (8 * DSTR)             // 8352 floats = 33408 B
__global__ void prep(const float* __restrict__ x,
                     const void* __restrict__ conn_raw,
                     const float* __restrict__ wgt) {
    const int tid = threadIdx.x;

    if (blockIdx.x >= 512) {
        // ---- x -> A fragment chunk (one uint4 per thread)
        int c = (blockIdx.x - 512) * 256 + tid;            // 0..65535
        int lane = c & 31, m16 = (c >> 5) & 31, kt16 = c >> 10;
        int g = lane >> 2, t = lane & 3;
        const float* r0 = x + (size_t)(m16 * 16 + g) * IN_FLAT;       // row g
        const float* r1 = r0 + 8 * IN_FLAT;                           // row g+8
        int k0 = kt16 * 16 + 2 * t;
        uint4 v;
        v.x = pack_h2(r0[k0],     r0[k0 + 1]);     // a0
        v.y = pack_h2(r1[k0],     r1[k0 + 1]);     // a1
        v.z = pack_h2(r0[k0 + 8], r0[k0 + 9]);     // a2
        v.w = pack_h2(r1[k0 + 8], r1[k0 + 9]);     // a3
        g_xA[c] = v;
        return;
    }

    // ---- densify: 8 neuron rows per block via f32 smem scatter
    extern __shared__ float ds[];
    const int n8g  = blockIdx.x;           // 0..511
    const int n16  = n8g >> 1;             // n16 group
    const int half = n8g & 1;              // 0: j0 rows, 1: j1 rows

    for (int i = tid; i < D_SM_FLOATS / 4; i += 256)
        ((float4*)ds)[i] = make_float4(0.f, 0.f, 0.f, 0.f);
    __syncthreads();

    const int* c32 = (const int*)conn_raw;
    bool is64 = true;                      // int64 dtype sniff (values < 1024)
    #pragma unroll
    for (int k = 1; k < 64; k += 2) is64 &= (c32[k] == 0);
    const long long* c64 = (const long long*)conn_raw;

    #pragma unroll
    for (int i = 0; i < 2; ++i) {
        int e = i * 256 + tid;                       // 0..511
        int nl = e >> 6, f = e & 63;
        size_t gi = (size_t)(n8g * 8 + nl) * FOCUS + f;
        int idx = is64 ? (int)c64[gi] : c32[gi];
        atomicAdd(ds + nl * DSTR + idx, wgt[gi]);
    }
    __syncthreads();

    // write the 8B half of each B fragment chunk this block owns
    uint2* outp = (uint2*)((char*)g_WB + half * 8);
    #pragma unroll
    for (int i = 0; i < 8; ++i) {
        int e    = i * 256 + tid;                    // 0..2047
        int kt16 = e >> 5, ln = e & 31;
        int g = ln >> 2, t = ln & 3;
        int k0 = kt16 * 16 + 2 * t;
        const float* w = ds + g * DSTR;              // local row g
        uint2 v;
        v.x = pack_h2(w[k0],     w[k0 + 1]);         // b0
        v.y = pack_h2(w[k0 + 8], w[k0 + 9]);         // b1
        outp[(((size_t)kt16 * 256 + n16) * 32 + ln) * 2] = v;
    }
}

// ---------------------------------------------------------------------------
// Main GEMM: out = x @ W^T + bias, fp16 m16n8k16, f32 accumulate.
// 4 warps (2x2), warp tile 64x64, BK=128, 3-stage cp.async; at the
// per-SMSP HMMA issue floor (~16 cyc/HMMA on sm_103a mma.sync).
// ---------------------------------------------------------------------------
__global__ void __launch_bounds__(TPB, 1)
gemm_f16(const float* __restrict__ bias, float* __restrict__ out) {
    extern __shared__ char smb[];
    const uint32_t sbase = smem_u32(smb);

    const int tid  = threadIdx.x;
    const int lane = tid & 31;
    const int wid  = tid >> 5;
    const int wm   = wid & 1;          // warp row -> m16 tiles {4wm..4wm+3}
    const int wn   = wid >> 1;         // warp col -> n16 tiles {4wn..4wn+3}
    const int n0   = blockIdx.x * BN;
    const int m0   = blockIdx.y * BM;

    *(float*)(smb + OF_BIAS + tid * 4) = bias[n0 + tid];

    const int mSlab = m0 >> 4;         // base m16 index (8 tiles)
    const int nSlab = n0 >> 4;         // base n16 index (8 tiles)

    // stage one BK=128 slab: smem layout per operand [ks 8][tile 8][lane 32].
    auto stage = [&](int kt, int s) {
        uint32_t db = sbase + (uint32_t)s * STAGE_BYTES;
        #pragma unroll
        for (int it = 0; it < 16; ++it) {
            int c    = it * 128 + tid;
            int ks   = c >> 8, tl = (c >> 5) & 7, ln = c & 31;
            int kt16 = kt * 8 + ks;
            cp_async16(db + (uint32_t)c * 16,
                       g_xA + ((size_t)kt16 * 32 + mSlab + tl) * 32 + ln);
            cp_async16(db + OF_B + (uint32_t)c * 16,
                       g_WB + ((size_t)kt16 * 256 + nSlab + tl) * 32 + ln);
        }
    };

    #pragma unroll
    for (int s = 0; s < STAGES - 1; ++s) {
        stage(s, s);
        asm volatile("cp.async.commit_group;" ::: "memory");
    }

    float acc[4][4][2][4] = {};   // [m16 i][n16 t][n8 j][c-reg]
    uint4 af[2][4], bf[2][4];     // register double buffer
    int slot = 0;

    for (int kt = 0; kt < KTILES; ++kt) {
        asm volatile("cp.async.wait_group %0;" :: "n"(STAGES - 2) : "memory");
        __syncthreads();

        // issue next slab's staging FIRST so it overlaps the whole HMMA stream
        int nk = kt + STAGES - 1;
        if (nk < KTILES) {
            int ns = slot + STAGES - 1; if (ns >= STAGES) ns -= STAGES;
            stage(nk, ns);               // ns != slot (compute buffer): safe
        }

        const char* tb  = smb + (size_t)slot * STAGE_BYTES;
        const char* pa  = tb +        (wm * 4 * 32 + lane) * 16;
        const char* pb  = tb + OF_B + (wn * 4 * 32 + lane) * 16;

        #pragma unroll
        for (int i = 0; i < 4; ++i) {
            af[0][i] = *(const uint4*)(pa + i * 512);
            bf[0][i] = *(const uint4*)(pb + i * 512);
        }

        #pragma unroll
        for (int ks = 0; ks < 8; ++ks) {
            const int cur = ks & 1, nxt = cur ^ 1;
            if (ks < 7) {               // prefetch ks+1 before issuing HMMAs
                const char* qa = pa + (ks + 1) * 4096;
                const char* qb = pb + (ks + 1) * 4096;
                #pragma unroll
                for (int i = 0; i < 4; ++i) {
                    af[nxt][i] = *(const uint4*)(qa + i * 512);
                    bf[nxt][i] = *(const uint4*)(qb + i * 512);
                }
            }
            #pragma unroll
            for (int i = 0; i < 4; ++i)
                #pragma unroll
                for (int t = 0; t < 4; ++t) {
                    mma_f16(acc[i][t][0], af[cur][i], bf[cur][t].x, bf[cur][t].y);
                    mma_f16(acc[i][t][1], af[cur][i], bf[cur][t].z, bf[cur][t].w);
                }
        }

        asm volatile("cp.async.commit_group;" ::: "memory");
        slot = slot == STAGES - 1 ? 0 : slot + 1;
    }

    // epilogue: bias add + float2 stores
    const int g = lane >> 2, q = lane & 3;
    const float* sb = (const float*)(smb + OF_BIAS);
    #pragma unroll
    for (int i = 0; i < 4; ++i) {
        #pragma unroll
        for (int hi = 0; hi < 2; ++hi) {
            int row = m0 + (wm * 4 + i) * 16 + hi * 8 + g;
            float* orow = out + (size_t)row * NEURONS + n0;
            #pragma unroll
            for (int t = 0; t < 4; ++t)
                #pragma unroll
                for (int j = 0; j < 2; ++j) {
                    int col = (wn * 4 + t) * 16 + j * 8 + q * 2;
                    float2 v = make_float2(acc[i][t][j][hi * 2 + 0] + sb[col],
                                           acc[i][t][j][hi * 2 + 1] + sb[col + 1]);
                    *(float2*)(orow + col) = v;
                }
        }
    }
}

// ---------------------------------------------------------------------------
extern "C" void kernel_launch(void* const* d_in, const int* in_sizes, int n_in,
                              void* d_out, int out_size) {
    const float* x    = (const float*)d_in[0];
    const void*  conn = d_in[1];                  // int64 (or int32) indices
    const float* wgt  = (const float*)d_in[2];
    const float* bias = (const float*)d_in[3];
    float* out = (float*)d_out;

    cudaFuncSetAttribute(gemm_f16,
                         cudaFuncAttributeMaxDynamicSharedMemorySize, SMEM_DYN);
    cudaFuncSetAttribute(prep,
                         cudaFuncAttributeMaxDynamicSharedMemorySize,
                         D_SM_FLOATS * 4);

    prep<<<768, 256, D_SM_FLOATS * 4>>>(x, conn, wgt);   // densify + convert

    dim3 grid(NEURONS / BN, BATCH / BM);                 // 32 x 4 = 128 blocks
    gemm_f16<<<grid, TPB, SMEM_DYN>>>(bias, out);
}

// round 14
// speedup vs baseline: 1.0904x; 1.0904x over previous
#include <cuda_runtime.h>
#include <cuda_fp16.h>
#include <stdint.h>

// Problem constants
#define BATCH   512
#define IN_FLAT 1024
#define NEURONS 4096
#define FOCUS   64

// GEMM tiling (fp16 m16n8k16)
#define BM 128
#define BN 128
#define BK 128
#define TPB 128                    // 4 warps (2m x 2n), warp tile 64x64
#define KTILES (IN_FLAT / BK)      // 8
#define STAGES 3
#define STAGE_BYTES 65536          // A 32KB + B 32KB (fp16)
#define OF_B 32768
#define OF_BIAS (STAGES * STAGE_BYTES)          // 196608
#define SMEM_DYN (OF_BIAS + BN * 4)             // 197120

// Fragment-packed operands (uint4 chunks; device globals, no allocation)
// A chunk (kt16, m16, lane) = {a0,a1,a2,a3} of m16n8k16   -> 64*32*32 uint4 = 1 MB
// B chunk (kt16, n16, lane) = {b0,b1 of n8 j0, b0,b1 j1}  -> 64*256*32 uint4 = 8 MB
__device__ uint4 g_xA[64 * 32 * 32];
__device__ uint4 g_WB[64 * 256 * 32];

// ---------------------------------------------------------------------------
__device__ __forceinline__ uint32_t smem_u32(const void* p) {
    uint32_t a;
    asm("{ .reg .u64 t; cvta.to.shared.u64 t, %1; cvt.u32.u64 %0, t; }" : "=r"(a) : "l"(p));
    return a;
}
__device__ __forceinline__ uint32_t pack_h2(float lo, float hi) {
    __half2 h = __floats2half2_rn(lo, hi);
    return *(uint32_t*)&h;
}
__device__ __forceinline__ void cp_async16(uint32_t sdst, const void* gsrc) {
    asm volatile("cp.async.cg.shared.global [%0], [%1], 16;"
                 :: "r"(sdst), "l"(__cvta_generic_to_global(gsrc)) : "memory");
}
__device__ __forceinline__ void mma_f16(float* c, const uint4& a,
                                        uint32_t b0, uint32_t b1) {
    asm volatile(
        "mma.sync.aligned.m16n8k16.row.col.f32.f16.f16.f32 "
        "{%0,%1,%2,%3}, {%4,%5,%6,%7}, {%8,%9}, {%0,%1,%2,%3};"
        : "+f"(c[0]), "+f"(c[1]), "+f"(c[2]), "+f"(c[3])
        : "r"(a.x), "r"(a.y), "r"(a.z), "r"(a.w), "r"(b0), "r"(b1));
}

// ---------------------------------------------------------------------------
// Merged prep kernel (1024 threads/block, grid 192) -> ~one wave on 148 SMs:
//   blocks [0,128):   densify 32 W rows each (f32 smem scatter) -> g_WB chunks
//   blocks [128,192): convert x (1 uint4 chunk per thread)      -> g_xA chunks
#define DSTR 1044                          // padded row stride (floats)
#define D_SM_FLOATS (32 * DSTR)            // 33408 floats = 133632 B
__global__ void __launch_bounds__(1024, 1)
prep(const float* __restrict__ x,
     const void* __restrict__ conn_raw,
     const float* __restrict__ wgt) {
    const int tid = threadIdx.x;

    if (blockIdx.x >= 128) {
        // ---- x -> A fragment chunk (one uint4 per thread)
        int c = (blockIdx.x - 128) * 1024 + tid;           // 0..65535
        int lane = c & 31, m16 = (c >> 5) & 31, kt16 = c >> 10;
        int g = lane >> 2, t = lane & 3;
        const float* r0 = x + (size_t)(m16 * 16 + g) * IN_FLAT;       // row g
        const float* r1 = r0 + 8 * IN_FLAT;                           // row g+8
        int k0 = kt16 * 16 + 2 * t;
        uint4 v;
        v.x = pack_h2(r0[k0],     r0[k0 + 1]);     // a0
        v.y = pack_h2(r1[k0],     r1[k0 + 1]);     // a1
        v.z = pack_h2(r0[k0 + 8], r0[k0 + 9]);     // a2
        v.w = pack_h2(r1[k0 + 8], r1[k0 + 9]);     // a3
        g_xA[c] = v;
        return;
    }

    // ---- densify: 32 neuron rows per block via f32 smem scatter
    extern __shared__ float ds[];
    const int n32g = blockIdx.x;           // 0..127 (rows 32*n32g .. +31)

    #pragma unroll
    for (int i = 0; i < D_SM_FLOATS / 4 / 1024 + 1; ++i) {
        int e = i * 1024 + tid;
        if (e < D_SM_FLOATS / 4)
            ((float4*)ds)[e] = make_float4(0.f, 0.f, 0.f, 0.f);
    }
    __syncthreads();

    const int* c32 = (const int*)conn_raw;
    bool is64 = true;                      // int64 dtype sniff (values < 1024)
    #pragma unroll
    for (int k = 1; k < 64; k += 2) is64 &= (c32[k] == 0);
    const long long* c64 = (const long long*)conn_raw;

    #pragma unroll
    for (int i = 0; i < 2; ++i) {
        int e = i * 1024 + tid;                      // 0..2047
        int nl = e >> 6, f = e & 63;
        size_t gi = (size_t)(n32g * 32 + nl) * FOCUS + f;
        int idx = is64 ? (int)c64[gi] : c32[gi];
        atomicAdd(ds + nl * DSTR + idx, wgt[gi]);
    }
    __syncthreads();

    // write B fragment chunks: 2 n16 groups x 64 kt16 x 32 lanes = 4096 uint4
    #pragma unroll
    for (int i = 0; i < 4; ++i) {
        int e    = i * 1024 + tid;                   // 0..4095
        int sub  = e >> 11;                          // which n16 half (0/1)
        int rem  = e & 2047;
        int kt16 = rem >> 5, ln = rem & 31;
        int g = ln >> 2, t = ln & 3;
        int k0 = kt16 * 16 + 2 * t;
        const float* w0 = ds + (sub * 16 + g) * DSTR;        // n8 j0 row
        const float* w1 = ds + (sub * 16 + g + 8) * DSTR;    // n8 j1 row
        uint4 v;
        v.x = pack_h2(w0[k0],     w0[k0 + 1]);       // j0.b0
        v.y = pack_h2(w0[k0 + 8], w0[k0 + 9]);       // j0.b1
        v.z = pack_h2(w1[k0],     w1[k0 + 1]);       // j1.b0
        v.w = pack_h2(w1[k0 + 8], w1[k0 + 9]);       // j1.b1
        int n16g = n32g * 2 + sub;
        g_WB[((size_t)kt16 * 256 + n16g) * 32 + ln] = v;
    }
}

// ---------------------------------------------------------------------------
// Main GEMM (R12 configuration — measured at the HMMA issue floor):
// 4 warps (2x2), warp tile 64x64, BK=128, 3-stage cp.async, register
// double-buffered fragments, staging issued before the HMMA stream.
// ---------------------------------------------------------------------------
__global__ void __launch_bounds__(TPB, 1)
gemm_f16(const float* __restrict__ bias, float* __restrict__ out) {
    extern __shared__ char smb[];
    const uint32_t sbase = smem_u32(smb);

    const int tid  = threadIdx.x;
    const int lane = tid & 31;
    const int wid  = tid >> 5;
    const int wm   = wid & 1;          // warp row -> m16 tiles {4wm..4wm+3}
    const int wn   = wid >> 1;         // warp col -> n16 tiles {4wn..4wn+3}
    const int n0   = blockIdx.x * BN;
    const int m0   = blockIdx.y * BM;

    *(float*)(smb + OF_BIAS + tid * 4) = bias[n0 + tid];

    const int mSlab = m0 >> 4;         // base m16 index (8 tiles)
    const int nSlab = n0 >> 4;         // base n16 index (8 tiles)

    // stage one BK=128 slab: smem layout per operand [ks 8][tile 8][lane 32].
    auto stage = [&](int kt, int s) {
        uint32_t db = sbase + (uint32_t)s * STAGE_BYTES;
        #pragma unroll
        for (int it = 0; it < 16; ++it) {
            int c    = it * 128 + tid;
            int ks   = c >> 8, tl = (c >> 5) & 7, ln = c & 31;
            int kt16 = kt * 8 + ks;
            cp_async16(db + (uint32_t)c * 16,
                       g_xA + ((size_t)kt16 * 32 + mSlab + tl) * 32 + ln);
            cp_async16(db + OF_B + (uint32_t)c * 16,
                       g_WB + ((size_t)kt16 * 256 + nSlab + tl) * 32 + ln);
        }
    };

    #pragma unroll
    for (int s = 0; s < STAGES - 1; ++s) {
        stage(s, s);
        asm volatile("cp.async.commit_group;" ::: "memory");
    }

    float acc[4][4][2][4] = {};   // [m16 i][n16 t][n8 j][c-reg]
    uint4 af[2][4], bf[2][4];     // register double buffer
    int slot = 0;

    for (int kt = 0; kt < KTILES; ++kt) {
        asm volatile("cp.async.wait_group %0;" :: "n"(STAGES - 2) : "memory");
        __syncthreads();

        // issue next slab's staging first so it overlaps the HMMA stream
        int nk = kt + STAGES - 1;
        if (nk < KTILES) {
            int ns = slot + STAGES - 1; if (ns >= STAGES) ns -= STAGES;
            stage(nk, ns);               // ns != slot (compute buffer): safe
        }

        const char* tb  = smb + (size_t)slot * STAGE_BYTES;
        const char* pa  = tb +        (wm * 4 * 32 + lane) * 16;
        const char* pb  = tb + OF_B + (wn * 4 * 32 + lane) * 16;

        #pragma unroll
        for (int i = 0; i < 4; ++i) {
            af[0][i] = *(const uint4*)(pa + i * 512);
            bf[0][i] = *(const uint4*)(pb + i * 512);
        }

        #pragma unroll
        for (int ks = 0; ks < 8; ++ks) {
            const int cur = ks & 1, nxt = cur ^ 1;
            if (ks < 7) {               // prefetch ks+1 before issuing HMMAs
                const char* qa = pa + (ks + 1) * 4096;
                const char* qb = pb + (ks + 1) * 4096;
                #pragma unroll
                for (int i = 0; i < 4; ++i) {
                    af[nxt][i] = *(const uint4*)(qa + i * 512);
                    bf[nxt][i] = *(const uint4*)(qb + i * 512);
                }
            }
            #pragma unroll
            for (int i = 0; i < 4; ++i)
                #pragma unroll
                for (int t = 0; t < 4; ++t) {
                    mma_f16(acc[i][t][0], af[cur][i], bf[cur][t].x, bf[cur][t].y);
                    mma_f16(acc[i][t][1], af[cur][i], bf[cur][t].z, bf[cur][t].w);
                }
        }

        asm volatile("cp.async.commit_group;" ::: "memory");
        slot = slot == STAGES - 1 ? 0 : slot + 1;
    }

    // epilogue: bias add + float2 stores
    const int g = lane >> 2, q = lane & 3;
    const float* sb = (const float*)(smb + OF_BIAS);
    #pragma unroll
    for (int i = 0; i < 4; ++i) {
        #pragma unroll
        for (int hi = 0; hi < 2; ++hi) {
            int row = m0 + (wm * 4 + i) * 16 + hi * 8 + g;
            float* orow = out + (size_t)row * NEURONS + n0;
            #pragma unroll
            for (int t = 0; t < 4; ++t)
                #pragma unroll
                for (int j = 0; j < 2; ++j) {
                    int col = (wn * 4 + t) * 16 + j * 8 + q * 2;
                    float2 v = make_float2(acc[i][t][j][hi * 2 + 0] + sb[col],
                                           acc[i][t][j][hi * 2 + 1] + sb[col + 1]);
                    *(float2*)(orow + col) = v;
                }
        }
    }
}

// ---------------------------------------------------------------------------
extern "C" void kernel_launch(void* const* d_in, const int* in_sizes, int n_in,
                              void* d_out, int out_size) {
    const float* x    = (const float*)d_in[0];
    const void*  conn = d_in[1];                  // int64 (or int32) indices
    const float* wgt  = (const float*)d_in[2];
    const float* bias = (const float*)d_in[3];
    float* out = (float*)d_out;

    cudaFuncSetAttribute(gemm_f16,
                         cudaFuncAttributeMaxDynamicSharedMemorySize, SMEM_DYN);
    cudaFuncSetAttribute(prep,
                         cudaFuncAttributeMaxDynamicSharedMemorySize,
                         D_SM_FLOATS * 4);

    prep<<<192, 1024, D_SM_FLOATS * 4>>>(x, conn, wgt);  // ~one wave

    dim3 grid(NEURONS / BN, BATCH / BM);                 // 32 x 4 = 128 blocks
    gemm_f16<<<grid, TPB, SMEM_DYN>>>(bias, out);
}